// round 7
// baseline (speedup 1.0000x reference)
#include <cuda_runtime.h>
#include <cuda_fp16.h>
#include <cstdint>
#include <cstddef>

// Problem dims (fixed)
#define KDIM 4096
#define NDIM 4096
#define TTOK 8192
#define NGROUPS 32

// ---------------- GEMM tiling (mma.sync path, compute_100-safe) -----------
#define BM 128
#define BN 128
#define BK 32
#define PADH 40                      // halfs per smem row (80B pitch, 16B aligned)
#define TILE_BYTES (BM * PADH * 2)   // 10240 per operand tile
#define STAGE_BYTES (2 * TILE_BYTES) // 20480 (A + B)
#define NSTAGE 3
#define GEMM_SMEM (NSTAGE * STAGE_BYTES)  // 61440
#define KITERS (KDIM / BK)           // 128

// ---------------- W-build ----------------
#define ROT_PITCH 132
#define BW_SMEM ((128 * ROT_PITCH + 4 * 128 + 16) * 4)

static constexpr float INV_SCALE = 0.08838834764831845f; // 1/sqrt(128)

// Scratch (allocation-free rule: __device__ globals)
__device__ __align__(16) __half g_xh[(size_t)TTOK * KDIM];  // 64 MB
__device__ __align__(16) __half g_wh[(size_t)NDIM * KDIM];  // 32 MB

// ---------------------------------------------------------------------------
// helpers
// ---------------------------------------------------------------------------
__device__ __forceinline__ uint32_t smem_u32(const void* p) {
    uint32_t a;
    asm("{ .reg .u64 t; cvta.to.shared.u64 t, %1; cvt.u32.u64 %0, t; }"
        : "=r"(a) : "l"(p));
    return a;
}

__device__ __forceinline__ void cp16(uint32_t dst, const void* src) {
    asm volatile("cp.async.cg.shared.global [%0], [%1], 16;\n"
                 :: "r"(dst), "l"(src));
}

__device__ __forceinline__ void ldmatrix_x4(uint32_t* r, uint32_t addr) {
    asm volatile("ldmatrix.sync.aligned.m8n8.x4.shared.b16 {%0,%1,%2,%3}, [%4];"
                 : "=r"(r[0]), "=r"(r[1]), "=r"(r[2]), "=r"(r[3]) : "r"(addr));
}

__device__ __forceinline__ void mma16816(float* c, const uint32_t* a,
                                         uint32_t b0, uint32_t b1) {
    asm volatile(
        "mma.sync.aligned.m16n8k16.row.col.f32.f16.f16.f32 "
        "{%0,%1,%2,%3}, {%4,%5,%6,%7}, {%8,%9}, {%0,%1,%2,%3};"
        : "+f"(c[0]), "+f"(c[1]), "+f"(c[2]), "+f"(c[3])
        : "r"(a[0]), "r"(a[1]), "r"(a[2]), "r"(a[3]), "r"(b0), "r"(b1));
}

// ---------------------------------------------------------------------------
// Kernel 1: x fp32 -> fp16
// ---------------------------------------------------------------------------
__global__ void convert_x_kernel(const float* __restrict__ x) {
    size_t i = ((size_t)blockIdx.x * blockDim.x + threadIdx.x) * 4;
    float4 v = *reinterpret_cast<const float4*>(x + i);
    union { __half2 h[2]; uint2 u; } pk;
    pk.h[0] = __floats2half2_rn(v.x, v.y);
    pk.h[1] = __floats2half2_rn(v.z, v.w);
    *reinterpret_cast<uint2*>(g_xh + i) = pk.u;
}

// ---------------------------------------------------------------------------
// Kernel 2: W''[n,k] = norm[n,g]/sqrt(128) * sum_j rot[g,j,k]*cb[idx[n,g,j]]
// ---------------------------------------------------------------------------
__global__ __launch_bounds__(128) void build_w_kernel(
    const int* __restrict__ idxp,      // (N, K/2) packed bytes as int32
    const float* __restrict__ cb,      // (16,)
    const float* __restrict__ norms,   // (N, 32)
    const float* __restrict__ rot)     // (32, 128, 128)
{
    extern __shared__ float sm[];
    float* rotT = sm;                       // [128][ROT_PITCH]
    float* sw   = sm + 128 * ROT_PITCH;     // [4][128]
    float* scb  = sw + 512;                 // [16]

    int g  = blockIdx.x;
    int n0 = blockIdx.y * 64;
    int tid = threadIdx.x;

    if (tid < 16) scb[tid] = cb[tid];
    const float* rg = rot + (size_t)g * 16384;
    for (int i = tid; i < 16384; i += 128) {
        int j = i >> 7, k = i & 127;
        rotT[k * ROT_PITCH + j] = rg[i];
    }
    __syncthreads();

    const float4* rp = reinterpret_cast<const float4*>(rotT + tid * ROT_PITCH);

    for (int q = 0; q < 16; q++) {
        #pragma unroll
        for (int i = tid; i < 256; i += 128) {
            int rr = i >> 6, cc = i & 63;
            int n = n0 + (q << 2) + rr;
            int p = idxp[(size_t)n * (KDIM / 2) + g * 64 + cc];
            sw[rr * 128 + 2 * cc]     = scb[p & 15];
            sw[rr * 128 + 2 * cc + 1] = scb[(p >> 4) & 15];
        }
        __syncthreads();

        float a0 = 0.f, a1 = 0.f, a2 = 0.f, a3 = 0.f;
        const float4* w0 = reinterpret_cast<const float4*>(sw);
        const float4* w1 = reinterpret_cast<const float4*>(sw + 128);
        const float4* w2 = reinterpret_cast<const float4*>(sw + 256);
        const float4* w3 = reinterpret_cast<const float4*>(sw + 384);
        #pragma unroll 8
        for (int j = 0; j < 32; j++) {
            float4 r4 = rp[j];
            float4 b;
            b = w0[j]; a0 = fmaf(r4.x,b.x,fmaf(r4.y,b.y,fmaf(r4.z,b.z,fmaf(r4.w,b.w,a0))));
            b = w1[j]; a1 = fmaf(r4.x,b.x,fmaf(r4.y,b.y,fmaf(r4.z,b.z,fmaf(r4.w,b.w,a1))));
            b = w2[j]; a2 = fmaf(r4.x,b.x,fmaf(r4.y,b.y,fmaf(r4.z,b.z,fmaf(r4.w,b.w,a2))));
            b = w3[j]; a3 = fmaf(r4.x,b.x,fmaf(r4.y,b.y,fmaf(r4.z,b.z,fmaf(r4.w,b.w,a3))));
        }

        int k = tid;
        #pragma unroll
        for (int rr = 0; rr < 4; rr++) {
            int n = n0 + (q << 2) + rr;
            float nm = norms[(size_t)n * NGROUPS + g] * INV_SCALE;
            float av = (rr == 0) ? a0 : (rr == 1) ? a1 : (rr == 2) ? a2 : a3;
            g_wh[(size_t)n * KDIM + g * 128 + k] = __float2half_rn(av * nm);
        }
        __syncthreads();
    }
}

// ---------------------------------------------------------------------------
// Kernel 3: GEMM out[t,n] = sum_k xh[t,k] * wh[n,k]
// mma.sync m16n8k16 fp16->fp32, 128x128 tile, 8 warps (2x4), warp tile 64x32,
// 3-stage cp.async pipeline, 80B-pitch smem (conflict-free ldmatrix).
// Grid: x = N tiles (fast) so a wave reuses a small set of A tiles in L2.
// ---------------------------------------------------------------------------
__device__ __forceinline__ void load_stage(uint32_t sb, int stage, int kt, int tid,
                                           const __half* Ag, const __half* Bg) {
    uint32_t sA = sb + stage * STAGE_BYTES;
    uint32_t sB = sA + TILE_BYTES;
    int k0 = kt * BK;
    #pragma unroll
    for (int i = 0; i < 2; i++) {
        int idx = tid + i * 256;              // 512 16B-chunks per operand
        int row = idx >> 2, cc = idx & 3;
        uint32_t off = (uint32_t)(row * (PADH * 2) + cc * 16);
        cp16(sA + off, Ag + (size_t)row * KDIM + k0 + cc * 8);
        cp16(sB + off, Bg + (size_t)row * KDIM + k0 + cc * 8);
    }
    asm volatile("cp.async.commit_group;\n" ::: "memory");
}

__global__ __launch_bounds__(256)
void gemm_kernel(float* __restrict__ out) {
    extern __shared__ char smem[];
    uint32_t sb = smem_u32(smem);
    int tid = threadIdx.x;
    int wid = tid >> 5, lane = tid & 31;
    int wm = wid >> 2;           // 0..1  (M)
    int wn = wid & 3;            // 0..3  (N)
    size_t m_base = (size_t)blockIdx.y * BM;
    size_t n_base = (size_t)blockIdx.x * BN;
    const __half* Ag = g_xh + m_base * KDIM;
    const __half* Bg = g_wh + n_base * KDIM;

    float acc[4][4][4];
    #pragma unroll
    for (int i = 0; i < 4; i++)
        #pragma unroll
        for (int j = 0; j < 4; j++)
            #pragma unroll
            for (int v = 0; v < 4; v++) acc[i][j][v] = 0.f;

    // ldmatrix per-lane address components
    int lrow = lane & 7;
    int lgrp = lane >> 3;        // 0..3
    // A x4: rows m0 + lrow + (grp&1)*8, k = k0 + (grp>=2)*8
    int a_row_off = lrow + ((lgrp & 1) << 3);
    int a_k_off   = (lgrp >> 1) << 3;
    // B x4: rows n0 + lrow + (grp>=2)*8, k = k0 + (grp&1)*8
    int b_row_off = lrow + ((lgrp >> 1) << 3);
    int b_k_off   = (lgrp & 1) << 3;

    // prologue: stages 0,1
    load_stage(sb, 0, 0, tid, Ag, Bg);
    load_stage(sb, 1, 1, tid, Ag, Bg);

    for (int it = 0; it < KITERS; it++) {
        asm volatile("cp.async.wait_group 1;\n" ::: "memory");
        __syncthreads();

        int nt_ = it + 2;
        if (nt_ < KITERS) {
            load_stage(sb, nt_ % NSTAGE, nt_, tid, Ag, Bg);
        } else {
            asm volatile("cp.async.commit_group;\n" ::: "memory");
        }

        uint32_t sA = sb + (it % NSTAGE) * STAGE_BYTES;
        uint32_t sB = sA + TILE_BYTES;

        #pragma unroll
        for (int ks = 0; ks < 2; ks++) {
            int k0 = ks * 16;
            uint32_t af[4][4];
            #pragma unroll
            for (int mt = 0; mt < 4; mt++) {
                uint32_t addr = sA
                    + (uint32_t)((wm * 64 + mt * 16 + a_row_off) * (PADH * 2))
                    + (uint32_t)((k0 + a_k_off) * 2);
                ldmatrix_x4(af[mt], addr);
            }
            uint32_t bf[2][4];
            #pragma unroll
            for (int bl = 0; bl < 2; bl++) {
                uint32_t addr = sB
                    + (uint32_t)((wn * 32 + bl * 16 + b_row_off) * (PADH * 2))
                    + (uint32_t)((k0 + b_k_off) * 2);
                ldmatrix_x4(bf[bl], addr);
            }
            #pragma unroll
            for (int mt = 0; mt < 4; mt++)
                #pragma unroll
                for (int nt = 0; nt < 4; nt++) {
                    int bl = nt >> 1, hf = nt & 1;
                    mma16816(acc[mt][nt], af[mt], bf[bl][hf * 2], bf[bl][hf * 2 + 1]);
                }
        }
    }

    // epilogue: direct register -> gmem (float2 stores)
    int qr = lane >> 2;          // 0..7
    int qc = (lane & 3) * 2;     // 0,2,4,6
    #pragma unroll
    for (int mt = 0; mt < 4; mt++) {
        size_t row0 = m_base + wm * 64 + mt * 16 + qr;
        #pragma unroll
        for (int nt = 0; nt < 4; nt++) {
            size_t col = n_base + wn * 32 + nt * 8 + qc;
            float2 v0 = make_float2(acc[mt][nt][0], acc[mt][nt][1]);
            float2 v1 = make_float2(acc[mt][nt][2], acc[mt][nt][3]);
            *reinterpret_cast<float2*>(out + row0 * NDIM + col) = v0;
            *reinterpret_cast<float2*>(out + (row0 + 8) * NDIM + col) = v1;
        }
    }
}

// ---------------------------------------------------------------------------
// Launch
// ---------------------------------------------------------------------------
extern "C" void kernel_launch(void* const* d_in, const int* in_sizes, int n_in,
                              void* d_out, int out_size) {
    const float* x     = (const float*)d_in[0];
    const int*   idxp  = (const int*)d_in[1];
    const float* cb    = (const float*)d_in[2];
    const float* norms = (const float*)d_in[3];
    const float* rot   = (const float*)d_in[4];
    float* out = (float*)d_out;

    cudaFuncSetAttribute(build_w_kernel,
                         cudaFuncAttributeMaxDynamicSharedMemorySize, BW_SMEM);
    cudaFuncSetAttribute(gemm_kernel,
                         cudaFuncAttributeMaxDynamicSharedMemorySize, GEMM_SMEM);

    // 1. x -> fp16
    convert_x_kernel<<<(TTOK * (size_t)KDIM) / (256 * 4), 256>>>(x);
    // 2. dequant + rotate + scale weights -> fp16
    build_w_kernel<<<dim3(NGROUPS, NDIM / 64), 128, BW_SMEM>>>(idxp, cb, norms, rot);
    // 3. GEMM (n-tiles fastest in grid -> small A working set per wave)
    gemm_kernel<<<dim3(NDIM / BN, TTOK / BM), 256, GEMM_SMEM>>>(out);
}

// round 8
// speedup vs baseline: 1.0826x; 1.0826x over previous
#include <cuda_runtime.h>
#include <cuda_fp16.h>
#include <cstdint>
#include <cstddef>

// Problem dims (fixed)
#define KDIM 4096
#define NDIM 4096
#define TTOK 8192
#define NGROUPS 32

// ---------------- GEMM tiling (mma.sync path, compute_100-safe) -----------
#define BM 128
#define BN 128
#define BK 32
#define PADH 40                      // halfs per smem row (80B pitch, 16B aligned)
#define TILE_BYTES (BM * PADH * 2)   // 10240 per operand tile
#define STAGE_BYTES (2 * TILE_BYTES) // 20480 (A + B)
#define NSTAGE 3
#define GEMM_SMEM (NSTAGE * STAGE_BYTES)  // 61440 -> 2 CTAs/SM fit in 228KB
#define KITERS (KDIM / BK)           // 128

// ---------------- W-build ----------------
#define ROT_PITCH 132
#define BW_SMEM ((128 * ROT_PITCH + 4 * 128 + 16) * 4)

static constexpr float INV_SCALE = 0.08838834764831845f; // 1/sqrt(128)

// Scratch (allocation-free rule: __device__ globals)
__device__ __align__(16) __half g_xh[(size_t)TTOK * KDIM];  // 64 MB
__device__ __align__(16) __half g_wh[(size_t)NDIM * KDIM];  // 32 MB

// ---------------------------------------------------------------------------
// helpers
// ---------------------------------------------------------------------------
__device__ __forceinline__ uint32_t smem_u32(const void* p) {
    uint32_t a;
    asm("{ .reg .u64 t; cvta.to.shared.u64 t, %1; cvt.u32.u64 %0, t; }"
        : "=r"(a) : "l"(p));
    return a;
}

__device__ __forceinline__ void cp16(uint32_t dst, const void* src) {
    asm volatile("cp.async.cg.shared.global [%0], [%1], 16;\n"
                 :: "r"(dst), "l"(src));
}

__device__ __forceinline__ void ldmatrix_x4(uint32_t* r, uint32_t addr) {
    asm volatile("ldmatrix.sync.aligned.m8n8.x4.shared.b16 {%0,%1,%2,%3}, [%4];"
                 : "=r"(r[0]), "=r"(r[1]), "=r"(r[2]), "=r"(r[3]) : "r"(addr));
}

__device__ __forceinline__ void mma16816(float* c, const uint32_t* a,
                                         uint32_t b0, uint32_t b1) {
    asm volatile(
        "mma.sync.aligned.m16n8k16.row.col.f32.f16.f16.f32 "
        "{%0,%1,%2,%3}, {%4,%5,%6,%7}, {%8,%9}, {%0,%1,%2,%3};"
        : "+f"(c[0]), "+f"(c[1]), "+f"(c[2]), "+f"(c[3])
        : "r"(a[0]), "r"(a[1]), "r"(a[2]), "r"(a[3]), "r"(b0), "r"(b1));
}

// ---------------------------------------------------------------------------
// Kernel 1: x fp32 -> fp16
// ---------------------------------------------------------------------------
__global__ void convert_x_kernel(const float* __restrict__ x) {
    size_t i = ((size_t)blockIdx.x * blockDim.x + threadIdx.x) * 4;
    float4 v = *reinterpret_cast<const float4*>(x + i);
    union { __half2 h[2]; uint2 u; } pk;
    pk.h[0] = __floats2half2_rn(v.x, v.y);
    pk.h[1] = __floats2half2_rn(v.z, v.w);
    *reinterpret_cast<uint2*>(g_xh + i) = pk.u;
}

// ---------------------------------------------------------------------------
// Kernel 2: W''[n,k] = norm[n,g]/sqrt(128) * sum_j rot[g,j,k]*cb[idx[n,g,j]]
// ---------------------------------------------------------------------------
__global__ __launch_bounds__(128) void build_w_kernel(
    const int* __restrict__ idxp,      // (N, K/2) packed bytes as int32
    const float* __restrict__ cb,      // (16,)
    const float* __restrict__ norms,   // (N, 32)
    const float* __restrict__ rot)     // (32, 128, 128)
{
    extern __shared__ float sm[];
    float* rotT = sm;                       // [128][ROT_PITCH]
    float* sw   = sm + 128 * ROT_PITCH;     // [4][128]
    float* scb  = sw + 512;                 // [16]

    int g  = blockIdx.x;
    int n0 = blockIdx.y * 64;
    int tid = threadIdx.x;

    if (tid < 16) scb[tid] = cb[tid];
    const float* rg = rot + (size_t)g * 16384;
    for (int i = tid; i < 16384; i += 128) {
        int j = i >> 7, k = i & 127;
        rotT[k * ROT_PITCH + j] = rg[i];
    }
    __syncthreads();

    const float4* rp = reinterpret_cast<const float4*>(rotT + tid * ROT_PITCH);

    for (int q = 0; q < 16; q++) {
        #pragma unroll
        for (int i = tid; i < 256; i += 128) {
            int rr = i >> 6, cc = i & 63;
            int n = n0 + (q << 2) + rr;
            int p = idxp[(size_t)n * (KDIM / 2) + g * 64 + cc];
            sw[rr * 128 + 2 * cc]     = scb[p & 15];
            sw[rr * 128 + 2 * cc + 1] = scb[(p >> 4) & 15];
        }
        __syncthreads();

        float a0 = 0.f, a1 = 0.f, a2 = 0.f, a3 = 0.f;
        const float4* w0 = reinterpret_cast<const float4*>(sw);
        const float4* w1 = reinterpret_cast<const float4*>(sw + 128);
        const float4* w2 = reinterpret_cast<const float4*>(sw + 256);
        const float4* w3 = reinterpret_cast<const float4*>(sw + 384);
        #pragma unroll 8
        for (int j = 0; j < 32; j++) {
            float4 r4 = rp[j];
            float4 b;
            b = w0[j]; a0 = fmaf(r4.x,b.x,fmaf(r4.y,b.y,fmaf(r4.z,b.z,fmaf(r4.w,b.w,a0))));
            b = w1[j]; a1 = fmaf(r4.x,b.x,fmaf(r4.y,b.y,fmaf(r4.z,b.z,fmaf(r4.w,b.w,a1))));
            b = w2[j]; a2 = fmaf(r4.x,b.x,fmaf(r4.y,b.y,fmaf(r4.z,b.z,fmaf(r4.w,b.w,a2))));
            b = w3[j]; a3 = fmaf(r4.x,b.x,fmaf(r4.y,b.y,fmaf(r4.z,b.z,fmaf(r4.w,b.w,a3))));
        }

        int k = tid;
        #pragma unroll
        for (int rr = 0; rr < 4; rr++) {
            int n = n0 + (q << 2) + rr;
            float nm = norms[(size_t)n * NGROUPS + g] * INV_SCALE;
            float av = (rr == 0) ? a0 : (rr == 1) ? a1 : (rr == 2) ? a2 : a3;
            g_wh[(size_t)n * KDIM + g * 128 + k] = __float2half_rn(av * nm);
        }
        __syncthreads();
    }
}

// ---------------------------------------------------------------------------
// Kernel 3: GEMM out[t,n] = sum_k xh[t,k] * wh[n,k]
// mma.sync m16n8k16 fp16->fp32, 128x128 tile, 8 warps (2x4), warp tile 64x32,
// 3-stage cp.async pipeline, 80B-pitch smem (conflict-free ldmatrix).
// __launch_bounds__(256, 2): cap regs at 128 so 2 CTAs co-reside per SM
// (16 warps, 4/SMSP) to cover the per-iter barrier + memory latency.
// ---------------------------------------------------------------------------
__device__ __forceinline__ void load_stage(uint32_t sb, int stage, int kt, int tid,
                                           const __half* Ag, const __half* Bg) {
    uint32_t sA = sb + stage * STAGE_BYTES;
    uint32_t sB = sA + TILE_BYTES;
    int k0 = kt * BK;
    #pragma unroll
    for (int i = 0; i < 2; i++) {
        int idx = tid + i * 256;              // 512 16B-chunks per operand
        int row = idx >> 2, cc = idx & 3;
        uint32_t off = (uint32_t)(row * (PADH * 2) + cc * 16);
        cp16(sA + off, Ag + (size_t)row * KDIM + k0 + cc * 8);
        cp16(sB + off, Bg + (size_t)row * KDIM + k0 + cc * 8);
    }
    asm volatile("cp.async.commit_group;\n" ::: "memory");
}

__global__ __launch_bounds__(256, 2)
void gemm_kernel(float* __restrict__ out) {
    extern __shared__ char smem[];
    uint32_t sb = smem_u32(smem);
    int tid = threadIdx.x;
    int wid = tid >> 5, lane = tid & 31;
    int wm = wid >> 2;           // 0..1  (M)
    int wn = wid & 3;            // 0..3  (N)
    size_t m_base = (size_t)blockIdx.y * BM;
    size_t n_base = (size_t)blockIdx.x * BN;
    const __half* Ag = g_xh + m_base * KDIM;
    const __half* Bg = g_wh + n_base * KDIM;

    float acc[4][4][4];
    #pragma unroll
    for (int i = 0; i < 4; i++)
        #pragma unroll
        for (int j = 0; j < 4; j++)
            #pragma unroll
            for (int v = 0; v < 4; v++) acc[i][j][v] = 0.f;

    // ldmatrix per-lane address components
    int lrow = lane & 7;
    int lgrp = lane >> 3;        // 0..3
    // A x4: rows m0 + lrow + (grp&1)*8, k = k0 + (grp>=2)*8
    int a_row_off = lrow + ((lgrp & 1) << 3);
    int a_k_off   = (lgrp >> 1) << 3;
    // B x4: rows n0 + lrow + (grp>=2)*8, k = k0 + (grp&1)*8
    int b_row_off = lrow + ((lgrp >> 1) << 3);
    int b_k_off   = (lgrp & 1) << 3;

    // Hoisted smem base addresses for fragment loads
    uint32_t aAddr0 = (uint32_t)((wm * 64 + a_row_off) * (PADH * 2) + a_k_off * 2);
    uint32_t bAddr0 = (uint32_t)((wn * 32 + b_row_off) * (PADH * 2) + b_k_off * 2);

    // prologue: stages 0,1
    load_stage(sb, 0, 0, tid, Ag, Bg);
    load_stage(sb, 1, 1, tid, Ag, Bg);

    for (int it = 0; it < KITERS; it++) {
        asm volatile("cp.async.wait_group 1;\n" ::: "memory");
        __syncthreads();

        int nt_ = it + 2;
        if (nt_ < KITERS) {
            load_stage(sb, nt_ % NSTAGE, nt_, tid, Ag, Bg);
        } else {
            asm volatile("cp.async.commit_group;\n" ::: "memory");
        }

        uint32_t sA = sb + (it % NSTAGE) * STAGE_BYTES;
        uint32_t sB = sA + TILE_BYTES;

        #pragma unroll
        for (int ks = 0; ks < 2; ks++) {
            uint32_t kofs = (uint32_t)(ks * 16 * 2);
            uint32_t af[4][4];
            #pragma unroll
            for (int mt = 0; mt < 4; mt++)
                ldmatrix_x4(af[mt], sA + aAddr0 + kofs
                            + (uint32_t)(mt * 16 * (PADH * 2)));
            uint32_t bf[2][4];
            #pragma unroll
            for (int bl = 0; bl < 2; bl++)
                ldmatrix_x4(bf[bl], sB + bAddr0 + kofs
                            + (uint32_t)(bl * 16 * (PADH * 2)));
            #pragma unroll
            for (int mt = 0; mt < 4; mt++)
                #pragma unroll
                for (int nt = 0; nt < 4; nt++) {
                    int bl = nt >> 1, hf = nt & 1;
                    mma16816(acc[mt][nt], af[mt], bf[bl][hf * 2], bf[bl][hf * 2 + 1]);
                }
        }
    }

    // epilogue: direct register -> gmem (float2 stores)
    int qr = lane >> 2;          // 0..7
    int qc = (lane & 3) * 2;     // 0,2,4,6
    #pragma unroll
    for (int mt = 0; mt < 4; mt++) {
        size_t row0 = m_base + wm * 64 + mt * 16 + qr;
        #pragma unroll
        for (int nt = 0; nt < 4; nt++) {
            size_t col = n_base + wn * 32 + nt * 8 + qc;
            float2 v0 = make_float2(acc[mt][nt][0], acc[mt][nt][1]);
            float2 v1 = make_float2(acc[mt][nt][2], acc[mt][nt][3]);
            *reinterpret_cast<float2*>(out + row0 * NDIM + col) = v0;
            *reinterpret_cast<float2*>(out + (row0 + 8) * NDIM + col) = v1;
        }
    }
}

// ---------------------------------------------------------------------------
// Launch
// ---------------------------------------------------------------------------
extern "C" void kernel_launch(void* const* d_in, const int* in_sizes, int n_in,
                              void* d_out, int out_size) {
    const float* x     = (const float*)d_in[0];
    const int*   idxp  = (const int*)d_in[1];
    const float* cb    = (const float*)d_in[2];
    const float* norms = (const float*)d_in[3];
    const float* rot   = (const float*)d_in[4];
    float* out = (float*)d_out;

    cudaFuncSetAttribute(build_w_kernel,
                         cudaFuncAttributeMaxDynamicSharedMemorySize, BW_SMEM);
    cudaFuncSetAttribute(gemm_kernel,
                         cudaFuncAttributeMaxDynamicSharedMemorySize, GEMM_SMEM);

    // 1. x -> fp16
    convert_x_kernel<<<(TTOK * (size_t)KDIM) / (256 * 4), 256>>>(x);
    // 2. dequant + rotate + scale weights -> fp16
    build_w_kernel<<<dim3(NGROUPS, NDIM / 64), 128, BW_SMEM>>>(idxp, cb, norms, rot);
    // 3. GEMM (n-tiles fastest in grid -> small A working set per wave)
    gemm_kernel<<<dim3(NDIM / BN, TTOK / BM), 256, GEMM_SMEM>>>(out);
}